// round 1
// baseline (speedup 1.0000x reference)
#include <cuda_runtime.h>

#define NN 20000
#define BB 64
#define EE 1280000

// Scratch: transposed x and transposed accumulator (allocation-free per rules).
__device__ float g_xT[NN * BB];    // xT[n*64 + b]
__device__ float g_accT[NN * BB];  // accT[n*64 + b]

// Kernel 1: zero accumulator + transpose x [B,N] -> xT [N,B].
__global__ void prep_kernel(const float* __restrict__ x) {
    int t = blockIdx.x * blockDim.x + threadIdx.x;
    if (t < NN * BB) {
        int b = t / NN;          // t coalesced over x (row-major [B, N])
        int n = t - b * NN;
        g_xT[n * BB + b] = x[t]; // scattered 4B stores, absorbed by L2
        g_accT[t] = 0.0f;
    }
}

// Kernel 2: edge scatter. One warp handles 32 edges: coalesced metadata load,
// then per-edge shfl broadcast; warp gathers xT[s] (64 floats = 2 lines,
// coalesced) and RED-adds into accT[d].
__global__ void scatter_kernel(const float* __restrict__ adj,
                               const float* __restrict__ w,
                               const int* __restrict__ src,
                               const int* __restrict__ dst) {
    int g = (blockIdx.x * blockDim.x + threadIdx.x) >> 5;  // warp-group id
    int lane = threadIdx.x & 31;
    int e = g * 32 + lane;
    if (e >= EE) return;  // EE % 32 == 0: whole warp exits together

    int   s = src[e];
    int   d = dst[e];
    float v = adj[e] * w[e];

    const float2* xT2 = (const float2*)g_xT;

    #pragma unroll 1
    for (int j = 0; j < 32; j++) {
        int   sj = __shfl_sync(0xffffffffu, s, j);
        int   dj = __shfl_sync(0xffffffffu, d, j);
        float vj = __shfl_sync(0xffffffffu, v, j);
        float2 xv = xT2[sj * 32 + lane];          // 256B coalesced, L2-hit
        float* accp = &g_accT[dj * 64 + 2 * lane];
        atomicAdd(accp,     vj * xv.x);            // RED (no return use)
        atomicAdd(accp + 1, vj * xv.y);
    }
}

// Kernel 3: epilogue. Tile-transpose accT [N,B] back to out [B,N] through
// smem, applying out = relu(acc * (x[0,n]*self_w[n]) + bias[n]).
__global__ void epilogue_kernel(const float* __restrict__ x,
                                const float* __restrict__ self_w,
                                const float* __restrict__ bias,
                                float* __restrict__ out) {
    __shared__ float tile[64][65];
    int n0 = blockIdx.x * 64;

    // Load: consecutive threads vary b -> coalesced 256B reads per n-row.
    for (int idx = threadIdx.x; idx < 64 * 64; idx += blockDim.x) {
        int nl = idx >> 6;
        int b  = idx & 63;
        int n  = n0 + nl;
        tile[nl][b] = (n < NN) ? g_accT[n * 64 + b] : 0.0f;
    }
    __syncthreads();

    // Store: consecutive threads vary n -> coalesced writes to out[b*N + n].
    for (int idx = threadIdx.x; idx < 64 * 64; idx += blockDim.x) {
        int b  = idx >> 6;
        int nl = idx & 63;
        int n  = n0 + nl;
        if (n < NN) {
            float sl = x[n] * self_w[n];   // x[0, n] — faithful reference quirk
            float vv = fmaf(tile[nl][b], sl, bias[n]);
            out[b * NN + n] = fmaxf(vv, 0.0f);
        }
    }
}

extern "C" void kernel_launch(void* const* d_in, const int* in_sizes, int n_in,
                              void* d_out, int out_size) {
    const float* x      = (const float*)d_in[0];
    const float* adj    = (const float*)d_in[1];
    const float* w      = (const float*)d_in[2];
    const float* self_w = (const float*)d_in[3];
    const float* bias   = (const float*)d_in[4];
    const int*   src    = (const int*)d_in[5];
    const int*   dst    = (const int*)d_in[6];
    float* out = (float*)d_out;

    prep_kernel<<<(NN * BB + 255) / 256, 256>>>(x);
    scatter_kernel<<<(EE / 32 + 7) / 8, 256>>>(adj, w, src, dst);
    epilogue_kernel<<<(NN + 63) / 64, 256>>>(x, self_w, bias, out);
}

// round 2
// speedup vs baseline: 1.6180x; 1.6180x over previous
#include <cuda_runtime.h>

#define NN 20000
#define BB 64
#define EE 1280000

// Scratch: transposed x and transposed accumulator (allocation-free per rules).
__device__ __align__(16) float g_xT[NN * BB];    // xT[n*64 + b]
__device__ __align__(16) float g_accT[NN * BB];  // accT[n*64 + b]

// Kernel 1: zero accumulator + transpose x [B,N] -> xT [N,B].
__global__ void prep_kernel(const float* __restrict__ x) {
    int t = blockIdx.x * blockDim.x + threadIdx.x;
    if (t < NN * BB) {
        int b = t / NN;          // t coalesced over x (row-major [B, N])
        int n = t - b * NN;
        g_xT[n * BB + b] = x[t]; // scattered 4B stores, absorbed by L2
        g_accT[t] = 0.0f;
    }
}

// Kernel 2: edge scatter, half-warp per edge.
// Each warp preloads 32 edges' metadata coalesced, then runs 16 iterations;
// per iteration lanes 0-15 process edge 2j, lanes 16-31 process edge 2j+1.
// Each lane: one LDG.128 gather of 4 batch values from xT (L2-resident,
// 16 lanes x 16B = fully coalesced 256B row) and ONE vector RED
// (red.global.add.v4.f32) into accT -- 4x fewer atomic ops than scalar.
__global__ void scatter_kernel(const float* __restrict__ adj,
                               const float* __restrict__ w,
                               const int* __restrict__ src,
                               const int* __restrict__ dst) {
    int g = (blockIdx.x * blockDim.x + threadIdx.x) >> 5;  // warp id
    int lane = threadIdx.x & 31;
    int e = g * 32 + lane;
    if (e >= EE) return;  // EE % 32 == 0: whole warp exits together

    int   s = src[e];
    int   d = dst[e];
    float v = adj[e] * w[e];

    int half = lane >> 4;        // 0: edge 2j, 1: edge 2j+1
    int ll   = lane & 15;        // lane within half-warp

    const float4* xT4 = (const float4*)g_xT;

    #pragma unroll 1
    for (int j = 0; j < 16; j++) {
        int sel = 2 * j + half;
        int   sj = __shfl_sync(0xffffffffu, s, sel);
        int   dj = __shfl_sync(0xffffffffu, d, sel);
        float vj = __shfl_sync(0xffffffffu, v, sel);

        float4 xv = xT4[sj * 16 + ll];           // LDG.128, coalesced, L2-hit
        float4 r;
        r.x = vj * xv.x;  r.y = vj * xv.y;
        r.z = vj * xv.z;  r.w = vj * xv.w;

        float* accp = &g_accT[dj * 64 + 4 * ll]; // 16B-aligned
        asm volatile("red.global.add.v4.f32 [%0], {%1, %2, %3, %4};"
                     :: "l"(accp), "f"(r.x), "f"(r.y), "f"(r.z), "f"(r.w)
                     : "memory");
    }
}

// Kernel 3: epilogue. Tile-transpose accT [N,B] back to out [B,N] through
// smem, applying out = relu(acc * (x[0,n]*self_w[n]) + bias[n]).
__global__ void epilogue_kernel(const float* __restrict__ x,
                                const float* __restrict__ self_w,
                                const float* __restrict__ bias,
                                float* __restrict__ out) {
    __shared__ float tile[64][65];
    int n0 = blockIdx.x * 64;

    // Load: consecutive threads vary b -> coalesced 256B reads per n-row.
    for (int idx = threadIdx.x; idx < 64 * 64; idx += blockDim.x) {
        int nl = idx >> 6;
        int b  = idx & 63;
        int n  = n0 + nl;
        tile[nl][b] = (n < NN) ? g_accT[n * 64 + b] : 0.0f;
    }
    __syncthreads();

    // Store: consecutive threads vary n -> coalesced writes to out[b*N + n].
    for (int idx = threadIdx.x; idx < 64 * 64; idx += blockDim.x) {
        int b  = idx >> 6;
        int nl = idx & 63;
        int n  = n0 + nl;
        if (n < NN) {
            float sl = x[n] * self_w[n];   // x[0, n] -- faithful reference quirk
            float vv = fmaf(tile[nl][b], sl, bias[n]);
            out[b * NN + n] = fmaxf(vv, 0.0f);
        }
    }
}

extern "C" void kernel_launch(void* const* d_in, const int* in_sizes, int n_in,
                              void* d_out, int out_size) {
    const float* x      = (const float*)d_in[0];
    const float* adj    = (const float*)d_in[1];
    const float* w      = (const float*)d_in[2];
    const float* self_w = (const float*)d_in[3];
    const float* bias   = (const float*)d_in[4];
    const int*   src    = (const int*)d_in[5];
    const int*   dst    = (const int*)d_in[6];
    float* out = (float*)d_out;

    prep_kernel<<<(NN * BB + 255) / 256, 256>>>(x);
    scatter_kernel<<<EE / 256, 256>>>(adj, w, src, dst);
    epilogue_kernel<<<(NN + 63) / 64, 256>>>(x, self_w, bias, out);
}